// round 10
// baseline (speedup 1.0000x reference)
#include <cuda_runtime.h>

static constexpr int Tn = 512;
static constexpr int Bn = 512;

// Scratch (device globals; allocation-free kernel_launch)
__device__ float g_seqA[(size_t)512 * 512 * 64];  // e1 out / d1 out
__device__ float g_seqB[(size_t)512 * 512 * 32];  // e2 out

__device__ __forceinline__ float fsig(float x) {
    return __fdividef(1.0f, 1.0f + __expf(-x));
}
__device__ __forceinline__ float ftanh(float x) {
    return 1.0f - __fdividef(2.0f, __expf(2.0f * x) + 1.0f);
}

// ---- packed f32x2 helpers (Blackwell) ----
__device__ __forceinline__ unsigned long long pk2(float lo, float hi) {
    unsigned long long r;
    asm("mov.b64 %0, {%1, %2};" : "=l"(r) : "f"(lo), "f"(hi));
    return r;
}
__device__ __forceinline__ void upk2(unsigned long long v, float& lo, float& hi) {
    asm("mov.b64 {%0, %1}, %2;" : "=f"(lo), "=f"(hi) : "l"(v));
}
__device__ __forceinline__ unsigned long long ffma2(
    unsigned long long a, unsigned long long b, unsigned long long c) {
    unsigned long long d;
    asm("fma.rn.f32x2 %0, %1, %2, %3;" : "=l"(d) : "l"(a), "l"(b), "l"(c));
    return d;
}

// ---------------------------------------------------------------------------
// FUSED LSTM layer: input projection + recurrent scan in one kernel.
// Block = 4H threads, R batch rows per block, grid = B/R.
// Thread j holds BOTH weight rows (Wih[j,:], Whh[j,:]) in packed registers.
// Per step: gate_j[r] = bias_j + Wih_j . x[r,t] + Whh_j . h[r,t-1]
// x staged via double-buffered SMEM with one-step-ahead LDG prefetch.
// Eliminates the xg intermediate (≈1.9 GB/call DRAM round-trip).
// ---------------------------------------------------------------------------
template <int IN, int H, int R>
__global__ void __launch_bounds__(4 * H) lstm_fused_kernel(
    const float* __restrict__ x,
    const float* __restrict__ Wih, const float* __restrict__ Whh,
    const float* __restrict__ bih, const float* __restrict__ bhh,
    float* __restrict__ hout)
{
    constexpr int G4 = 4 * H;
    constexpr int NPRE = (R * IN + G4 - 1) / G4;  // prefetch elems per thread

    __shared__ __align__(16) float x_sm[2][R][IN];
    __shared__ __align__(16) float h_sm[R][H];
    __shared__ float g_sm[R][G4];

    const int j = threadIdx.x;
    const int b0 = blockIdx.x * R;
    const int gate = j / H;

    // Weight rows in packed registers
    unsigned long long wx[IN / 2], wh[H / 2];
    {
        const unsigned long long* p = (const unsigned long long*)(Wih + (size_t)j * IN);
#pragma unroll
        for (int i = 0; i < IN / 2; i++) wx[i] = p[i];
        const unsigned long long* q = (const unsigned long long*)(Whh + (size_t)j * H);
#pragma unroll
        for (int k = 0; k < H / 2; k++) wh[k] = q[k];
    }
    const float bias = bih[j] + bhh[j];

    // x prefetch lane setup (fixed per thread across all t)
    const float* xsrc[NPRE];
    int xdst[NPRE];
    bool xval[NPRE];
#pragma unroll
    for (int u = 0; u < NPRE; u++) {
        const int i = j + u * G4;
        xval[u] = (i < R * IN);
        const int r = xval[u] ? (i / IN) : 0;
        const int col = xval[u] ? (i % IN) : 0;
        xsrc[u] = x + ((size_t)(b0 + r) * Tn) * IN + col;
        xdst[u] = xval[u] ? i : 0;
    }

    // init h = 0, preload x[t=0]
    for (int i = j; i < R * H; i += G4) ((float*)h_sm)[i] = 0.0f;
#pragma unroll
    for (int u = 0; u < NPRE; u++)
        if (xval[u]) ((float*)x_sm[0])[xdst[u]] = xsrc[u][0];

    float c = 0.0f;

    // cell-update mapping (threads j < R*H)
    const int cr = (j < R * H) ? (j / H) : 0;
    const int cm = (j < R * H) ? (j % H) : 0;
    float* hptr = hout + ((size_t)(b0 + cr) * Tn) * H + cm;

    __syncthreads();

    for (int t = 0; t < Tn; t++) {
        const int cur = t & 1;
        const int nxt = cur ^ 1;

        // Issue next-step x loads early (consumed after this step's barriers)
        float xpre[NPRE];
        const bool dopre = (t + 1 < Tn);
        if (dopre) {
#pragma unroll
            for (int u = 0; u < NPRE; u++)
                if (xval[u]) xpre[u] = xsrc[u][(size_t)(t + 1) * IN];
        }

        // Gate matvec: bias + Wih.x + Whh.h (independent chains across r)
        unsigned long long acc[R];
#pragma unroll
        for (int r = 0; r < R; r++) acc[r] = pk2(bias, 0.0f);

#pragma unroll
        for (int k = 0; k < IN / 4; k++) {
#pragma unroll
            for (int r = 0; r < R; r++) {
                ulonglong2 xv = ((const ulonglong2*)x_sm[cur][r])[k];
                acc[r] = ffma2(wx[2 * k + 0], xv.x, acc[r]);
                acc[r] = ffma2(wx[2 * k + 1], xv.y, acc[r]);
            }
        }
#pragma unroll
        for (int k = 0; k < H / 4; k++) {
#pragma unroll
            for (int r = 0; r < R; r++) {
                ulonglong2 hv = ((const ulonglong2*)h_sm[r])[k];
                acc[r] = ffma2(wh[2 * k + 0], hv.x, acc[r]);
                acc[r] = ffma2(wh[2 * k + 1], hv.y, acc[r]);
            }
        }

#pragma unroll
        for (int r = 0; r < R; r++) {
            float lo, hi;
            upk2(acc[r], lo, hi);
            float a = lo + hi;
            a = (gate == 2) ? ftanh(a) : fsig(a);
            g_sm[r][j] = a;
        }

        // Stash prefetched x into the other buffer (safe: that buffer was
        // last read two barriers ago)
        if (dopre) {
#pragma unroll
            for (int u = 0; u < NPRE; u++)
                if (xval[u]) ((float*)x_sm[nxt])[xdst[u]] = xpre[u];
        }
        __syncthreads();

        if (j < R * H) {
            const float iv = g_sm[cr][0 * H + cm];
            const float fv = g_sm[cr][1 * H + cm];
            const float gv = g_sm[cr][2 * H + cm];
            const float ov = g_sm[cr][3 * H + cm];
            c = fv * c + iv * gv;
            const float h = ov * ftanh(c);
            h_sm[cr][cm] = h;
            hptr[(size_t)t * H] = h;
        }
        __syncthreads();
    }
}

// ---------------------------------------------------------------------------
extern "C" void kernel_launch(void* const* d_in, const int* in_sizes, int n_in,
                              void* d_out, int out_size)
{
    (void)in_sizes; (void)n_in; (void)out_size;

    const float* x    = (const float*)d_in[0];
    const float* e1W  = (const float*)d_in[1];
    const float* e1U  = (const float*)d_in[2];
    const float* e1bi = (const float*)d_in[3];
    const float* e1bh = (const float*)d_in[4];
    const float* e2W  = (const float*)d_in[5];
    const float* e2U  = (const float*)d_in[6];
    const float* e2bi = (const float*)d_in[7];
    const float* e2bh = (const float*)d_in[8];
    const float* d1W  = (const float*)d_in[9];
    const float* d1U  = (const float*)d_in[10];
    const float* d1bi = (const float*)d_in[11];
    const float* d1bh = (const float*)d_in[12];
    const float* d2W  = (const float*)d_in[13];
    const float* d2U  = (const float*)d_in[14];
    const float* d2bi = (const float*)d_in[15];
    const float* d2bh = (const float*)d_in[16];
    float* out = (float*)d_out;

    float *sa = nullptr, *sb = nullptr;
    cudaGetSymbolAddress((void**)&sa, g_seqA);
    cudaGetSymbolAddress((void**)&sb, g_seqB);

    // e1: 72 -> 64   (R=4, grid 128: single wave, 1 CTA/SM — reg-bound)
    lstm_fused_kernel<72, 64, 4><<<Bn / 4, 256>>>(x, e1W, e1U, e1bi, e1bh, sa);
    // e2: 64 -> 32   (R=2, grid 256: single wave, 2 CTAs/SM)
    lstm_fused_kernel<64, 32, 2><<<Bn / 2, 128>>>(sa, e2W, e2U, e2bi, e2bh, sb);
    // d1: 32 -> 64   (R=2, grid 256: single wave, 2 CTAs/SM)
    lstm_fused_kernel<32, 64, 2><<<Bn / 2, 256>>>(sb, d1W, d1U, d1bi, d1bh, sa);
    // d2: 64 -> 72   (R=4, grid 128: single wave, 1 CTA/SM — reg-bound)
    lstm_fused_kernel<64, 72, 4><<<Bn / 4, 288>>>(sa, d2W, d2U, d2bi, d2bh, out);
}

// round 11
// speedup vs baseline: 1.0425x; 1.0425x over previous
#include <cuda_runtime.h>

static constexpr int Tn = 512;
static constexpr int Bn = 512;
static constexpr long BTn = (long)Bn * Tn;

// Scratch (device globals; allocation-free kernel_launch)
__device__ float g_xg[(size_t)512 * 512 * 288];   // max 4H = 288
__device__ float g_seqA[(size_t)512 * 512 * 64];  // e1 out / d1 out
__device__ float g_seqB[(size_t)512 * 512 * 32];  // e2 out

__device__ __forceinline__ float fsig(float x) {
    return __fdividef(1.0f, 1.0f + __expf(-x));
}
__device__ __forceinline__ float ftanh(float x) {
    return 1.0f - __fdividef(2.0f, __expf(2.0f * x) + 1.0f);
}

// ---- packed f32x2 helpers (Blackwell) ----
__device__ __forceinline__ unsigned long long pk2(float lo, float hi) {
    unsigned long long r;
    asm("mov.b64 %0, {%1, %2};" : "=l"(r) : "f"(lo), "f"(hi));
    return r;
}
__device__ __forceinline__ void upk2(unsigned long long v, float& lo, float& hi) {
    asm("mov.b64 {%0, %1}, %2;" : "=f"(lo), "=f"(hi) : "l"(v));
}
__device__ __forceinline__ unsigned long long ffma2(
    unsigned long long a, unsigned long long b, unsigned long long c) {
    unsigned long long d;
    asm("fma.rn.f32x2 %0, %1, %2, %3;" : "=l"(d) : "l"(a), "l"(b), "l"(c));
    return d;
}

// ---------------------------------------------------------------------------
// Input-projection GEMM (exact R2 structure — measured best).
// ---------------------------------------------------------------------------
template <int IN, int G>
__global__ void __launch_bounds__(G, 2) gemm_xg_kernel(
    const float* __restrict__ in, const float* __restrict__ Wih,
    const float* __restrict__ bih, const float* __restrict__ bhh,
    float* __restrict__ xg)
{
    constexpr int ROWS = 128;
    __shared__ __align__(16) float sIn[ROWS * IN];

    const int g = threadIdx.x;
    const size_t row0 = (size_t)blockIdx.x * ROWS;

    {
        const float4* src = (const float4*)(in + row0 * IN);
        float4* dst = (float4*)sIn;
        constexpr int NV = ROWS * IN / 4;
        for (int i = g; i < NV; i += G) dst[i] = src[i];
    }

    unsigned long long w2[IN / 2];
    {
        const unsigned long long* wp = (const unsigned long long*)(Wih + (size_t)g * IN);
#pragma unroll
        for (int i = 0; i < IN / 2; i++) w2[i] = wp[i];
    }
    const float bias = bih[g] + bhh[g];

    __syncthreads();

    float* outp = xg + row0 * G + g;
#pragma unroll 1
    for (int r = 0; r < ROWS; r++) {
        unsigned long long accA = pk2(bias, 0.0f);
        unsigned long long accB = pk2(0.0f, 0.0f);
        const ulonglong2* rp = (const ulonglong2*)(sIn + r * IN);
#pragma unroll
        for (int i = 0; i < IN / 4; i++) {
            ulonglong2 v = rp[i];
            accA = ffma2(w2[2 * i + 0], v.x, accA);
            accB = ffma2(w2[2 * i + 1], v.y, accB);
        }
        float a0, a1, b0, b1;
        upk2(accA, a0, a1);
        upk2(accB, b0, b1);
        outp[(size_t)r * G] = (a0 + a1) + (b0 + b1);
    }
}

// ---------------------------------------------------------------------------
// Recurrent scan (R2 structure). THIS ROUND: R=1 / grid=B for ALL layers,
// with MINB=2 for H=64/72 (128-reg cap -> NO spill of the 64/72-reg w2).
// ---------------------------------------------------------------------------
template <int H, int R, int MINB>
__global__ void __launch_bounds__(4 * H, MINB) lstm_rec_kernel(
    const float* __restrict__ xg, const float* __restrict__ Whh,
    float* __restrict__ hout)
{
    constexpr int G4 = 4 * H;
    __shared__ __align__(16) float h_sm[R * H];
    __shared__ float g_sm[R * G4];

    const int j = threadIdx.x;
    const int b0 = blockIdx.x * R;
    const int gate = j / H;

    unsigned long long w2[H / 2];
    {
        const unsigned long long* wp = (const unsigned long long*)(Whh + (size_t)j * H);
#pragma unroll
        for (int k = 0; k < H / 2; k++) w2[k] = wp[k];
    }

    for (int i = j; i < R * H; i += G4) h_sm[i] = 0.0f;
    float c = 0.0f;

    const float* xgp = xg + (size_t)b0 * Tn * G4 + j;
    float* hp = hout + (size_t)b0 * Tn * H;

    const int cr = j / H;  // cell-update mapping (first R*H threads)
    const int cm = j % H;

    float xn[R];
#pragma unroll
    for (int r = 0; r < R; r++) xn[r] = xgp[(size_t)r * Tn * G4];

    __syncthreads();

    for (int t = 0; t < Tn; t++) {
        unsigned long long acc[R];
#pragma unroll
        for (int r = 0; r < R; r++) acc[r] = pk2(xn[r], 0.0f);

        if (t + 1 < Tn) {
#pragma unroll
            for (int r = 0; r < R; r++)
                xn[r] = xgp[((size_t)r * Tn + t + 1) * G4];
        }

#pragma unroll
        for (int k = 0; k < H / 4; k++) {
#pragma unroll
            for (int r = 0; r < R; r++) {
                ulonglong2 hv = ((const ulonglong2*)&h_sm[r * H])[k];
                acc[r] = ffma2(w2[2 * k + 0], hv.x, acc[r]);
                acc[r] = ffma2(w2[2 * k + 1], hv.y, acc[r]);
            }
        }

#pragma unroll
        for (int r = 0; r < R; r++) {
            float lo, hi;
            upk2(acc[r], lo, hi);
            float a = lo + hi;
            a = (gate == 2) ? ftanh(a) : fsig(a);
            g_sm[r * G4 + j] = a;
        }
        __syncthreads();

        if (j < R * H) {
            const float iv = g_sm[cr * G4 + 0 * H + cm];
            const float fv = g_sm[cr * G4 + 1 * H + cm];
            const float gv = g_sm[cr * G4 + 2 * H + cm];
            const float ov = g_sm[cr * G4 + 3 * H + cm];
            c = fv * c + iv * gv;
            const float h = ov * ftanh(c);
            h_sm[cr * H + cm] = h;
            hp[((size_t)cr * Tn + t) * H + cm] = h;
        }
        __syncthreads();
    }
}

// ---------------------------------------------------------------------------
extern "C" void kernel_launch(void* const* d_in, const int* in_sizes, int n_in,
                              void* d_out, int out_size)
{
    (void)in_sizes; (void)n_in; (void)out_size;

    const float* x    = (const float*)d_in[0];
    const float* e1W  = (const float*)d_in[1];
    const float* e1U  = (const float*)d_in[2];
    const float* e1bi = (const float*)d_in[3];
    const float* e1bh = (const float*)d_in[4];
    const float* e2W  = (const float*)d_in[5];
    const float* e2U  = (const float*)d_in[6];
    const float* e2bi = (const float*)d_in[7];
    const float* e2bh = (const float*)d_in[8];
    const float* d1W  = (const float*)d_in[9];
    const float* d1U  = (const float*)d_in[10];
    const float* d1bi = (const float*)d_in[11];
    const float* d1bh = (const float*)d_in[12];
    const float* d2W  = (const float*)d_in[13];
    const float* d2U  = (const float*)d_in[14];
    const float* d2bi = (const float*)d_in[15];
    const float* d2bh = (const float*)d_in[16];
    float* out = (float*)d_out;

    float *xg = nullptr, *sa = nullptr, *sb = nullptr;
    cudaGetSymbolAddress((void**)&xg, g_xg);
    cudaGetSymbolAddress((void**)&sa, g_seqA);
    cudaGetSymbolAddress((void**)&sb, g_seqB);

    const int gemmGrid = (int)(BTn / 128);  // 2048

    // e1: 72 -> 64   (rec: R=1, grid 512, MINB=2 -> 128-reg cap, no spill)
    gemm_xg_kernel<72, 256><<<gemmGrid, 256>>>(x, e1W, e1bi, e1bh, xg);
    lstm_rec_kernel<64, 1, 2><<<Bn, 256>>>(xg, e1U, sa);
    // e2: 64 -> 32   (proven best config)
    gemm_xg_kernel<64, 128><<<gemmGrid, 128>>>(sa, e2W, e2bi, e2bh, xg);
    lstm_rec_kernel<32, 1, 4><<<Bn, 128>>>(xg, e2U, sb);
    // d1: 32 -> 64
    gemm_xg_kernel<32, 256><<<gemmGrid, 256>>>(sb, d1W, d1bi, d1bh, xg);
    lstm_rec_kernel<64, 1, 2><<<Bn, 256>>>(xg, d1U, sa);
    // d2: 64 -> 72   (R=1, grid 512, MINB=2 -> no spill of 72-reg w2)
    gemm_xg_kernel<64, 288><<<gemmGrid, 288>>>(sa, d2W, d2bi, d2bh, xg);
    lstm_rec_kernel<72, 1, 2><<<Bn, 288>>>(xg, d2U, out);
}

// round 13
// speedup vs baseline: 1.1583x; 1.1111x over previous
#include <cuda_runtime.h>

static constexpr int Tn = 512;
static constexpr int Bn = 512;
static constexpr int NCH = 4;         // time chunks
static constexpr int CH = Tn / NCH;   // 128 steps per chunk

// Per-layer buffers (stages never share a buffer -> no WAR across pipeline)
__device__ float g_xg1[(size_t)512 * 512 * 256];
__device__ float g_xg2[(size_t)512 * 512 * 128];
__device__ float g_xg3[(size_t)512 * 512 * 256];
__device__ float g_xg4[(size_t)512 * 512 * 288];
__device__ float g_o1[(size_t)512 * 512 * 64];
__device__ float g_o2[(size_t)512 * 512 * 32];
__device__ float g_o3[(size_t)512 * 512 * 64];
__device__ float g_stH[4][512 * 72];
__device__ float g_stC[4][512 * 72];

__device__ __forceinline__ float fsig(float x) {
    return __fdividef(1.0f, 1.0f + __expf(-x));
}
__device__ __forceinline__ float ftanh(float x) {
    return 1.0f - __fdividef(2.0f, __expf(2.0f * x) + 1.0f);
}
__device__ __forceinline__ unsigned long long pk2(float lo, float hi) {
    unsigned long long r;
    asm("mov.b64 %0, {%1, %2};" : "=l"(r) : "f"(lo), "f"(hi));
    return r;
}
__device__ __forceinline__ void upk2(unsigned long long v, float& lo, float& hi) {
    asm("mov.b64 {%0, %1}, %2;" : "=f"(lo), "=f"(hi) : "l"(v));
}
__device__ __forceinline__ unsigned long long ffma2(
    unsigned long long a, unsigned long long b, unsigned long long c) {
    unsigned long long d;
    asm("fma.rn.f32x2 %0, %1, %2, %3;" : "=l"(d) : "l"(a), "l"(b), "l"(c));
    return d;
}

struct Ptrs {
    const float *x;
    const float *W0, *U0, *bi0, *bh0;
    const float *W1, *U1, *bi1, *bh1;
    const float *W2, *U2, *bi2, *bh2;
    const float *W3, *U3, *bi3, *bh3;
    float *xg1, *xg2, *xg3, *xg4;
    float *o1, *o2, *o3, *out;
    float *H0, *C0, *H1, *C1, *H2, *C2, *H3, *C3;
};
struct Wave {
    int n;
    int type[4];
    int start[4];
    int t0[4];
};

// ---- GEMM handler (proven R2 math), one batch row-chunk per block ----
template <int IN, int G>
__device__ void gemm_dev(float* sIn, int b, int t0,
    const float* __restrict__ in, const float* __restrict__ Wih,
    const float* __restrict__ bih, const float* __restrict__ bhh,
    float* __restrict__ xg)
{
    const int tid = threadIdx.x;
    const size_t row0 = (size_t)b * Tn + t0;
    {
        const float4* src = (const float4*)(in + row0 * IN);
        float4* dst = (float4*)sIn;
        constexpr int NV = CH * IN / 4;
        for (int i = tid; i < NV; i += 288) dst[i] = src[i];
    }
    unsigned long long w2[IN / 2];
    float bias = 0.0f;
    if (tid < G) {
        const unsigned long long* wp = (const unsigned long long*)(Wih + (size_t)tid * IN);
#pragma unroll
        for (int i = 0; i < IN / 2; i++) w2[i] = wp[i];
        bias = bih[tid] + bhh[tid];
    }
    __syncthreads();
    if (tid < G) {
        float* outp = xg + row0 * G + tid;
#pragma unroll 1
        for (int r = 0; r < CH; r++) {
            unsigned long long aA = pk2(bias, 0.0f);
            unsigned long long aB = pk2(0.0f, 0.0f);
            const ulonglong2* rp = (const ulonglong2*)(sIn + r * IN);
#pragma unroll
            for (int i = 0; i < IN / 4; i++) {
                ulonglong2 v = rp[i];
                aA = ffma2(w2[2 * i + 0], v.x, aA);
                aB = ffma2(w2[2 * i + 1], v.y, aB);
            }
            float a0, a1, b0, b1;
            upk2(aA, a0, a1);
            upk2(aB, b0, b1);
            outp[(size_t)r * G] = (a0 + a1) + (b0 + b1);
        }
    }
}

// ---- Recurrent chunk handler (proven R2 structure + h/c state carry) ----
template <int H, int R>
__device__ void rec_dev(float* sbuf, int lb, int t0,
    const float* __restrict__ xg, const float* __restrict__ Whh,
    float* __restrict__ hout, float* __restrict__ stH, float* __restrict__ stC)
{
    constexpr int G4 = 4 * H;
    float* h_sm = sbuf;            // R*H
    float* g_sm = sbuf + R * H;    // R*G4

    const int j = threadIdx.x;
    const bool act = (j < G4);
    const int b0 = lb * R;
    const int gate = act ? (j / H) : 0;
    const int cr = j / H;  // valid when j < R*H
    const int cm = j % H;

    unsigned long long w2[H / 2];
    if (act) {
        const unsigned long long* wp = (const unsigned long long*)(Whh + (size_t)j * H);
#pragma unroll
        for (int k = 0; k < H / 2; k++) w2[k] = wp[k];
    }

    float c = 0.0f;
    if (j < R * H) {
        float hv = 0.0f;
        if (t0 != 0) {
            hv = stH[(b0 + cr) * H + cm];
            c  = stC[(b0 + cr) * H + cm];
        }
        h_sm[cr * H + cm] = hv;
    }

    const float* xgp = xg + (size_t)b0 * Tn * G4 + j;
    float* hp = hout + (size_t)b0 * Tn * H;

    float xn[R];
    if (act) {
#pragma unroll
        for (int r = 0; r < R; r++) xn[r] = xgp[((size_t)r * Tn + t0) * G4];
    }
    __syncthreads();

    for (int t = t0; t < t0 + CH; t++) {
        if (act) {
            unsigned long long acc[R];
#pragma unroll
            for (int r = 0; r < R; r++) acc[r] = pk2(xn[r], 0.0f);
            if (t + 1 < t0 + CH) {
#pragma unroll
                for (int r = 0; r < R; r++)
                    xn[r] = xgp[((size_t)r * Tn + t + 1) * G4];
            }
#pragma unroll
            for (int k = 0; k < H / 4; k++) {
#pragma unroll
                for (int r = 0; r < R; r++) {
                    ulonglong2 hv = ((const ulonglong2*)&h_sm[r * H])[k];
                    acc[r] = ffma2(w2[2 * k + 0], hv.x, acc[r]);
                    acc[r] = ffma2(w2[2 * k + 1], hv.y, acc[r]);
                }
            }
#pragma unroll
            for (int r = 0; r < R; r++) {
                float lo, hi;
                upk2(acc[r], lo, hi);
                float a = lo + hi;
                a = (gate == 2) ? ftanh(a) : fsig(a);
                g_sm[r * G4 + j] = a;
            }
        }
        __syncthreads();

        if (j < R * H) {
            const float iv = g_sm[cr * G4 + 0 * H + cm];
            const float fv = g_sm[cr * G4 + 1 * H + cm];
            const float gv = g_sm[cr * G4 + 2 * H + cm];
            const float ov = g_sm[cr * G4 + 3 * H + cm];
            c = fv * c + iv * gv;
            const float h = ov * ftanh(c);
            h_sm[cr * H + cm] = h;
            hp[((size_t)cr * Tn + t) * H + cm] = h;
        }
        __syncthreads();
    }

    if (j < R * H) {
        stH[(b0 + cr) * H + cm] = h_sm[cr * H + cm];
        stC[(b0 + cr) * H + cm] = c;
    }
}

// ---- One pipeline wavefront: up to 4 independent (stage, chunk) tasks ----
__global__ void __launch_bounds__(288, 2) wave_kernel(Wave w, Ptrs p)
{
    __shared__ __align__(16) float sbuf[CH * 72];  // 36864 B, max task need

    const int bid = blockIdx.x;
    int slot = 0;
#pragma unroll
    for (int i = 1; i < 4; i++)
        if (i < w.n && bid >= w.start[i]) slot = i;
    const int lb = bid - w.start[slot];
    const int t0 = w.t0[slot];

    switch (w.type[slot]) {
        case 0: gemm_dev<72, 256>(sbuf, lb, t0, p.x,  p.W0, p.bi0, p.bh0, p.xg1); break;
        case 1: rec_dev<64, 2>(sbuf, lb, t0, p.xg1, p.U0, p.o1, p.H0, p.C0); break;
        case 2: gemm_dev<64, 128>(sbuf, lb, t0, p.o1, p.W1, p.bi1, p.bh1, p.xg2); break;
        case 3: rec_dev<32, 1>(sbuf, lb, t0, p.xg2, p.U1, p.o2, p.H1, p.C1); break;
        case 4: gemm_dev<32, 256>(sbuf, lb, t0, p.o2, p.W2, p.bi2, p.bh2, p.xg3); break;
        case 5: rec_dev<64, 2>(sbuf, lb, t0, p.xg3, p.U2, p.o3, p.H2, p.C2); break;
        case 6: gemm_dev<64, 288>(sbuf, lb, t0, p.o3, p.W3, p.bi3, p.bh3, p.xg4); break;
        case 7: rec_dev<72, 2>(sbuf, lb, t0, p.xg4, p.U3, p.out, p.H3, p.C3); break;
    }
}

// ---------------------------------------------------------------------------
extern "C" void kernel_launch(void* const* d_in, const int* in_sizes, int n_in,
                              void* d_out, int out_size)
{
    (void)in_sizes; (void)n_in; (void)out_size;

    Ptrs p;
    p.x   = (const float*)d_in[0];
    p.W0  = (const float*)d_in[1];  p.U0 = (const float*)d_in[2];
    p.bi0 = (const float*)d_in[3];  p.bh0 = (const float*)d_in[4];
    p.W1  = (const float*)d_in[5];  p.U1 = (const float*)d_in[6];
    p.bi1 = (const float*)d_in[7];  p.bh1 = (const float*)d_in[8];
    p.W2  = (const float*)d_in[9];  p.U2 = (const float*)d_in[10];
    p.bi2 = (const float*)d_in[11]; p.bh2 = (const float*)d_in[12];
    p.W3  = (const float*)d_in[13]; p.U3 = (const float*)d_in[14];
    p.bi3 = (const float*)d_in[15]; p.bh3 = (const float*)d_in[16];
    p.out = (float*)d_out;

    float *stH, *stC;
    cudaGetSymbolAddress((void**)&p.xg1, g_xg1);
    cudaGetSymbolAddress((void**)&p.xg2, g_xg2);
    cudaGetSymbolAddress((void**)&p.xg3, g_xg3);
    cudaGetSymbolAddress((void**)&p.xg4, g_xg4);
    cudaGetSymbolAddress((void**)&p.o1, g_o1);
    cudaGetSymbolAddress((void**)&p.o2, g_o2);
    cudaGetSymbolAddress((void**)&p.o3, g_o3);
    cudaGetSymbolAddress((void**)&stH, g_stH);
    cudaGetSymbolAddress((void**)&stC, g_stC);
    p.H0 = stH + 0 * 512 * 72; p.C0 = stC + 0 * 512 * 72;
    p.H1 = stH + 1 * 512 * 72; p.C1 = stC + 1 * 512 * 72;
    p.H2 = stH + 2 * 512 * 72; p.C2 = stC + 2 * 512 * 72;
    p.H3 = stH + 3 * 512 * 72; p.C3 = stC + 3 * 512 * 72;

    // Blocks per stage type: gemm stages (even) and rec stages (odd)
    const int nb[8] = {Bn, Bn / 2, Bn, Bn, Bn, Bn / 2, Bn, Bn / 2};

    // Wavefront schedule: all (s, c) with s + c = k are independent.
    for (int k = 0; k <= 10; k++) {
        Wave w;
        w.n = 0;
        int total = 0;
        // rec tasks first (long serial poles), then gemm backfill
        for (int pass = 0; pass < 2; pass++) {
            for (int c = 0; c < NCH; c++) {
                const int s = k - c;
                if (s < 0 || s > 7) continue;
                const bool isRec = (s & 1);
                if ((pass == 0) != isRec) continue;
                w.type[w.n] = s;
                w.t0[w.n] = c * CH;
                w.start[w.n] = total;
                total += nb[s];
                w.n++;
            }
        }
        if (w.n == 0) continue;
        wave_kernel<<<total, 288>>>(w, p);
    }
}

// round 14
// speedup vs baseline: 1.2356x; 1.0668x over previous
#include <cuda_runtime.h>

static constexpr int Tn = 512;
static constexpr int Bn = 512;
static constexpr long BTn = (long)Bn * Tn;

// Scratch (device globals; allocation-free kernel_launch)
__device__ float g_xg[(size_t)512 * 512 * 288];   // max 4H = 288
__device__ float g_seqA[(size_t)512 * 512 * 64];  // e1 out / d1 out
__device__ float g_seqB[(size_t)512 * 512 * 32];  // e2 out

__device__ __forceinline__ float fsig(float x) {
    return __fdividef(1.0f, 1.0f + __expf(-x));
}
__device__ __forceinline__ float ftanh(float x) {
    return 1.0f - __fdividef(2.0f, __expf(2.0f * x) + 1.0f);
}

// ---- packed f32x2 helpers (Blackwell) ----
__device__ __forceinline__ unsigned long long pk2(float lo, float hi) {
    unsigned long long r;
    asm("mov.b64 %0, {%1, %2};" : "=l"(r) : "f"(lo), "f"(hi));
    return r;
}
__device__ __forceinline__ void upk2(unsigned long long v, float& lo, float& hi) {
    asm("mov.b64 {%0, %1}, %2;" : "=f"(lo), "=f"(hi) : "l"(v));
}
__device__ __forceinline__ unsigned long long ffma2(
    unsigned long long a, unsigned long long b, unsigned long long c) {
    unsigned long long d;
    asm("fma.rn.f32x2 %0, %1, %2, %3;" : "=l"(d) : "l"(a), "l"(b), "l"(c));
    return d;
}

// ---------------------------------------------------------------------------
// Input-projection GEMM (exact R2 structure — measured best).
// ---------------------------------------------------------------------------
template <int IN, int G>
__global__ void __launch_bounds__(G, 2) gemm_xg_kernel(
    const float* __restrict__ in, const float* __restrict__ Wih,
    const float* __restrict__ bih, const float* __restrict__ bhh,
    float* __restrict__ xg)
{
    constexpr int ROWS = 128;
    __shared__ __align__(16) float sIn[ROWS * IN];

    const int g = threadIdx.x;
    const size_t row0 = (size_t)blockIdx.x * ROWS;

    {
        const float4* src = (const float4*)(in + row0 * IN);
        float4* dst = (float4*)sIn;
        constexpr int NV = ROWS * IN / 4;
        for (int i = g; i < NV; i += G) dst[i] = src[i];
    }

    unsigned long long w2[IN / 2];
    {
        const unsigned long long* wp = (const unsigned long long*)(Wih + (size_t)g * IN);
#pragma unroll
        for (int i = 0; i < IN / 2; i++) w2[i] = wp[i];
    }
    const float bias = bih[g] + bhh[g];

    __syncthreads();

    float* outp = xg + row0 * G + g;
#pragma unroll 1
    for (int r = 0; r < ROWS; r++) {
        unsigned long long accA = pk2(bias, 0.0f);
        unsigned long long accB = pk2(0.0f, 0.0f);
        const ulonglong2* rp = (const ulonglong2*)(sIn + r * IN);
#pragma unroll
        for (int i = 0; i < IN / 4; i++) {
            ulonglong2 v = rp[i];
            accA = ffma2(w2[2 * i + 0], v.x, accA);
            accB = ffma2(w2[2 * i + 1], v.y, accB);
        }
        float a0, a1, b0, b1;
        upk2(accA, a0, a1);
        upk2(accB, b0, b1);
        outp[(size_t)r * G] = (a0 + a1) + (b0 + b1);
    }
}

// ---------------------------------------------------------------------------
// Recurrent scan (proven R2 structure: block=4H, R rows/block, 2 barriers
// per step). THIS ROUND: xg prefetch depth 1 -> 4. xn is a register ring
// xn[R][4]; the time loop is unrolled x4 so ring indices are static.
// Load->use distance ~4 steps covers the ~577cyc DRAM latency of the
// out-of-L2 xg stream (the per-step head stall seen as 1540 cyc/step).
// ---------------------------------------------------------------------------
template <int H, int R, int MINB>
__global__ void __launch_bounds__(4 * H, MINB) lstm_rec_kernel(
    const float* __restrict__ xg, const float* __restrict__ Whh,
    float* __restrict__ hout)
{
    constexpr int G4 = 4 * H;
    constexpr int D = 4;  // prefetch depth (Tn % D == 0)
    __shared__ __align__(16) float h_sm[R * H];
    __shared__ float g_sm[R * G4];

    const int j = threadIdx.x;
    const int b0 = blockIdx.x * R;
    const int gate = j / H;

    unsigned long long w2[H / 2];
    {
        const unsigned long long* wp = (const unsigned long long*)(Whh + (size_t)j * H);
#pragma unroll
        for (int k = 0; k < H / 2; k++) w2[k] = wp[k];
    }

    for (int i = j; i < R * H; i += G4) h_sm[i] = 0.0f;
    float c = 0.0f;

    const float* xgp = xg + (size_t)b0 * Tn * G4 + j;
    float* hp = hout + (size_t)b0 * Tn * H;

    const int cr = j / H;  // cell-update mapping (first R*H threads)
    const int cm = j % H;

    // prime the prefetch ring: steps 0..D-1
    float xn[R][D];
#pragma unroll
    for (int u = 0; u < D; u++)
#pragma unroll
        for (int r = 0; r < R; r++)
            xn[r][u] = xgp[((size_t)r * Tn + u) * G4];

    __syncthreads();

#pragma unroll 1
    for (int t = 0; t < Tn; t += D) {
#pragma unroll
        for (int u = 0; u < D; u++) {
            const int tt = t + u;

            unsigned long long acc[R];
#pragma unroll
            for (int r = 0; r < R; r++) acc[r] = pk2(xn[r][u], 0.0f);

            // refill ring slot u with step tt+D (consumed D steps later)
            if (tt + D < Tn) {
#pragma unroll
                for (int r = 0; r < R; r++)
                    xn[r][u] = xgp[((size_t)r * Tn + tt + D) * G4];
            }

#pragma unroll
            for (int k = 0; k < H / 4; k++) {
#pragma unroll
                for (int r = 0; r < R; r++) {
                    ulonglong2 hv = ((const ulonglong2*)&h_sm[r * H])[k];
                    acc[r] = ffma2(w2[2 * k + 0], hv.x, acc[r]);
                    acc[r] = ffma2(w2[2 * k + 1], hv.y, acc[r]);
                }
            }

#pragma unroll
            for (int r = 0; r < R; r++) {
                float lo, hi;
                upk2(acc[r], lo, hi);
                float a = lo + hi;
                a = (gate == 2) ? ftanh(a) : fsig(a);
                g_sm[r * G4 + j] = a;
            }
            __syncthreads();

            if (j < R * H) {
                const float iv = g_sm[cr * G4 + 0 * H + cm];
                const float fv = g_sm[cr * G4 + 1 * H + cm];
                const float gv = g_sm[cr * G4 + 2 * H + cm];
                const float ov = g_sm[cr * G4 + 3 * H + cm];
                c = fv * c + iv * gv;
                const float h = ov * ftanh(c);
                h_sm[cr * H + cm] = h;
                hp[((size_t)cr * Tn + tt) * H + cm] = h;
            }
            __syncthreads();
        }
    }
}

// ---------------------------------------------------------------------------
extern "C" void kernel_launch(void* const* d_in, const int* in_sizes, int n_in,
                              void* d_out, int out_size)
{
    (void)in_sizes; (void)n_in; (void)out_size;

    const float* x    = (const float*)d_in[0];
    const float* e1W  = (const float*)d_in[1];
    const float* e1U  = (const float*)d_in[2];
    const float* e1bi = (const float*)d_in[3];
    const float* e1bh = (const float*)d_in[4];
    const float* e2W  = (const float*)d_in[5];
    const float* e2U  = (const float*)d_in[6];
    const float* e2bi = (const float*)d_in[7];
    const float* e2bh = (const float*)d_in[8];
    const float* d1W  = (const float*)d_in[9];
    const float* d1U  = (const float*)d_in[10];
    const float* d1bi = (const float*)d_in[11];
    const float* d1bh = (const float*)d_in[12];
    const float* d2W  = (const float*)d_in[13];
    const float* d2U  = (const float*)d_in[14];
    const float* d2bi = (const float*)d_in[15];
    const float* d2bh = (const float*)d_in[16];
    float* out = (float*)d_out;

    float *xg = nullptr, *sa = nullptr, *sb = nullptr;
    cudaGetSymbolAddress((void**)&xg, g_xg);
    cudaGetSymbolAddress((void**)&sa, g_seqA);
    cudaGetSymbolAddress((void**)&sb, g_seqB);

    const int gemmGrid = (int)(BTn / 128);  // 2048

    // e1: 72 -> 64
    gemm_xg_kernel<72, 256><<<gemmGrid, 256>>>(x, e1W, e1bi, e1bh, xg);
    lstm_rec_kernel<64, 2, 2><<<Bn / 2, 256>>>(xg, e1U, sa);
    // e2: 64 -> 32
    gemm_xg_kernel<64, 128><<<gemmGrid, 128>>>(sa, e2W, e2bi, e2bh, xg);
    lstm_rec_kernel<32, 1, 4><<<Bn, 128>>>(xg, e2U, sb);
    // d1: 32 -> 64
    gemm_xg_kernel<32, 256><<<gemmGrid, 256>>>(sb, d1W, d1bi, d1bh, xg);
    lstm_rec_kernel<64, 2, 2><<<Bn / 2, 256>>>(xg, d1U, sa);
    // d2: 64 -> 72
    gemm_xg_kernel<64, 288><<<gemmGrid, 288>>>(sa, d2W, d2bi, d2bh, xg);
    lstm_rec_kernel<72, 2, 2><<<Bn / 2, 288>>>(xg, d2U, out);
}

// round 15
// speedup vs baseline: 1.3059x; 1.0569x over previous
#include <cuda_runtime.h>

static constexpr int Tn = 512;
static constexpr int Bn = 512;
static constexpr long BTn = (long)Bn * Tn;

// Scratch (device globals; allocation-free kernel_launch)
__device__ float g_xg[(size_t)512 * 512 * 288];   // max 4H = 288
__device__ float g_seqA[(size_t)512 * 512 * 64];  // e1 out / d1 out
__device__ float g_seqB[(size_t)512 * 512 * 32];  // e2 out

__device__ __forceinline__ float fsig(float x) {
    return __fdividef(1.0f, 1.0f + __expf(-x));
}
__device__ __forceinline__ float ftanh(float x) {
    return 1.0f - __fdividef(2.0f, __expf(2.0f * x) + 1.0f);
}

// ---- packed f32x2 helpers (Blackwell) ----
__device__ __forceinline__ unsigned long long pk2(float lo, float hi) {
    unsigned long long r;
    asm("mov.b64 %0, {%1, %2};" : "=l"(r) : "f"(lo), "f"(hi));
    return r;
}
__device__ __forceinline__ void upk2(unsigned long long v, float& lo, float& hi) {
    asm("mov.b64 {%0, %1}, %2;" : "=f"(lo), "=f"(hi) : "l"(v));
}
__device__ __forceinline__ unsigned long long ffma2(
    unsigned long long a, unsigned long long b, unsigned long long c) {
    unsigned long long d;
    asm("fma.rn.f32x2 %0, %1, %2, %3;" : "=l"(d) : "l"(a), "l"(b), "l"(c));
    return d;
}

// ---------------------------------------------------------------------------
// Input-projection GEMM (exact R2 structure — measured best).
// ---------------------------------------------------------------------------
template <int IN, int G>
__global__ void __launch_bounds__(G, 2) gemm_xg_kernel(
    const float* __restrict__ in, const float* __restrict__ Wih,
    const float* __restrict__ bih, const float* __restrict__ bhh,
    float* __restrict__ xg)
{
    constexpr int ROWS = 128;
    __shared__ __align__(16) float sIn[ROWS * IN];

    const int g = threadIdx.x;
    const size_t row0 = (size_t)blockIdx.x * ROWS;

    {
        const float4* src = (const float4*)(in + row0 * IN);
        float4* dst = (float4*)sIn;
        constexpr int NV = ROWS * IN / 4;
        for (int i = g; i < NV; i += G) dst[i] = src[i];
    }

    unsigned long long w2[IN / 2];
    {
        const unsigned long long* wp = (const unsigned long long*)(Wih + (size_t)g * IN);
#pragma unroll
        for (int i = 0; i < IN / 2; i++) w2[i] = wp[i];
    }
    const float bias = bih[g] + bhh[g];

    __syncthreads();

    float* outp = xg + row0 * G + g;
#pragma unroll 1
    for (int r = 0; r < ROWS; r++) {
        unsigned long long accA = pk2(bias, 0.0f);
        unsigned long long accB = pk2(0.0f, 0.0f);
        const ulonglong2* rp = (const ulonglong2*)(sIn + r * IN);
#pragma unroll
        for (int i = 0; i < IN / 4; i++) {
            ulonglong2 v = rp[i];
            accA = ffma2(w2[2 * i + 0], v.x, accA);
            accB = ffma2(w2[2 * i + 1], v.y, accB);
        }
        float a0, a1, b0, b1;
        upk2(accA, a0, a1);
        upk2(accB, b0, b1);
        outp[(size_t)r * G] = (a0 + a1) + (b0 + b1);
    }
}

// ---------------------------------------------------------------------------
// Recurrent scan (proven R2 structure) with register-ring xg prefetch of
// depth D. D is chosen per layer so the x-D unrolled step body fits the
// 6KB L0 I$: H=32 -> D=4 (proven -31%), H=64/72 -> D=2.
// ---------------------------------------------------------------------------
template <int H, int R, int MINB, int D>
__global__ void __launch_bounds__(4 * H, MINB) lstm_rec_kernel(
    const float* __restrict__ xg, const float* __restrict__ Whh,
    float* __restrict__ hout)
{
    constexpr int G4 = 4 * H;
    __shared__ __align__(16) float h_sm[R * H];
    __shared__ float g_sm[R * G4];

    const int j = threadIdx.x;
    const int b0 = blockIdx.x * R;
    const int gate = j / H;

    unsigned long long w2[H / 2];
    {
        const unsigned long long* wp = (const unsigned long long*)(Whh + (size_t)j * H);
#pragma unroll
        for (int k = 0; k < H / 2; k++) w2[k] = wp[k];
    }

    for (int i = j; i < R * H; i += G4) h_sm[i] = 0.0f;
    float c = 0.0f;

    const float* xgp = xg + (size_t)b0 * Tn * G4 + j;
    float* hp = hout + (size_t)b0 * Tn * H;

    const int cr = j / H;  // cell-update mapping (first R*H threads)
    const int cm = j % H;

    // prime the prefetch ring: steps 0..D-1
    float xn[R][D];
#pragma unroll
    for (int u = 0; u < D; u++)
#pragma unroll
        for (int r = 0; r < R; r++)
            xn[r][u] = xgp[((size_t)r * Tn + u) * G4];

    __syncthreads();

#pragma unroll 1
    for (int t = 0; t < Tn; t += D) {
#pragma unroll
        for (int u = 0; u < D; u++) {
            const int tt = t + u;

            unsigned long long acc[R];
#pragma unroll
            for (int r = 0; r < R; r++) acc[r] = pk2(xn[r][u], 0.0f);

            // refill ring slot u with step tt+D (consumed D steps later)
            if (tt + D < Tn) {
#pragma unroll
                for (int r = 0; r < R; r++)
                    xn[r][u] = xgp[((size_t)r * Tn + tt + D) * G4];
            }

#pragma unroll
            for (int k = 0; k < H / 4; k++) {
#pragma unroll
                for (int r = 0; r < R; r++) {
                    ulonglong2 hv = ((const ulonglong2*)&h_sm[r * H])[k];
                    acc[r] = ffma2(w2[2 * k + 0], hv.x, acc[r]);
                    acc[r] = ffma2(w2[2 * k + 1], hv.y, acc[r]);
                }
            }

#pragma unroll
            for (int r = 0; r < R; r++) {
                float lo, hi;
                upk2(acc[r], lo, hi);
                float a = lo + hi;
                a = (gate == 2) ? ftanh(a) : fsig(a);
                g_sm[r * G4 + j] = a;
            }
            __syncthreads();

            if (j < R * H) {
                const float iv = g_sm[cr * G4 + 0 * H + cm];
                const float fv = g_sm[cr * G4 + 1 * H + cm];
                const float gv = g_sm[cr * G4 + 2 * H + cm];
                const float ov = g_sm[cr * G4 + 3 * H + cm];
                c = fv * c + iv * gv;
                const float h = ov * ftanh(c);
                h_sm[cr * H + cm] = h;
                hp[((size_t)cr * Tn + tt) * H + cm] = h;
            }
            __syncthreads();
        }
    }
}

// ---------------------------------------------------------------------------
extern "C" void kernel_launch(void* const* d_in, const int* in_sizes, int n_in,
                              void* d_out, int out_size)
{
    (void)in_sizes; (void)n_in; (void)out_size;

    const float* x    = (const float*)d_in[0];
    const float* e1W  = (const float*)d_in[1];
    const float* e1U  = (const float*)d_in[2];
    const float* e1bi = (const float*)d_in[3];
    const float* e1bh = (const float*)d_in[4];
    const float* e2W  = (const float*)d_in[5];
    const float* e2U  = (const float*)d_in[6];
    const float* e2bi = (const float*)d_in[7];
    const float* e2bh = (const float*)d_in[8];
    const float* d1W  = (const float*)d_in[9];
    const float* d1U  = (const float*)d_in[10];
    const float* d1bi = (const float*)d_in[11];
    const float* d1bh = (const float*)d_in[12];
    const float* d2W  = (const float*)d_in[13];
    const float* d2U  = (const float*)d_in[14];
    const float* d2bi = (const float*)d_in[15];
    const float* d2bh = (const float*)d_in[16];
    float* out = (float*)d_out;

    float *xg = nullptr, *sa = nullptr, *sb = nullptr;
    cudaGetSymbolAddress((void**)&xg, g_xg);
    cudaGetSymbolAddress((void**)&sa, g_seqA);
    cudaGetSymbolAddress((void**)&sb, g_seqB);

    const int gemmGrid = (int)(BTn / 128);  // 2048

    // e1: 72 -> 64   (rec: D=2 — unrolled body fits L0 I$)
    gemm_xg_kernel<72, 256><<<gemmGrid, 256>>>(x, e1W, e1bi, e1bh, xg);
    lstm_rec_kernel<64, 2, 2, 2><<<Bn / 2, 256>>>(xg, e1U, sa);
    // e2: 64 -> 32   (rec: D=4 — proven -31%)
    gemm_xg_kernel<64, 128><<<gemmGrid, 128>>>(sa, e2W, e2bi, e2bh, xg);
    lstm_rec_kernel<32, 1, 4, 4><<<Bn, 128>>>(xg, e2U, sb);
    // d1: 32 -> 64   (rec: D=2)
    gemm_xg_kernel<32, 256><<<gemmGrid, 256>>>(sb, d1W, d1bi, d1bh, xg);
    lstm_rec_kernel<64, 2, 2, 2><<<Bn / 2, 256>>>(xg, d1U, sa);
    // d2: 64 -> 72   (rec: D=2)
    gemm_xg_kernel<64, 288><<<gemmGrid, 288>>>(sa, d2W, d2bi, d2bh, xg);
    lstm_rec_kernel<72, 2, 2, 2><<<Bn / 2, 288>>>(xg, d2U, out);
}

// round 17
// speedup vs baseline: 1.3102x; 1.0033x over previous
#include <cuda_runtime.h>
#include <cstdint>

static constexpr int Tn = 512;
static constexpr int Bn = 512;
static constexpr long BTn = (long)Bn * Tn;

// Scratch (device globals; allocation-free kernel_launch)
__device__ float g_xg[(size_t)512 * 512 * 288];   // max 4H = 288
__device__ float g_seqA[(size_t)512 * 512 * 64];  // e1 out / d1 out
__device__ float g_seqB[(size_t)512 * 512 * 32];  // e2 out

__device__ __forceinline__ float fsig(float x) {
    return __fdividef(1.0f, 1.0f + __expf(-x));
}
__device__ __forceinline__ float ftanh(float x) {
    return 1.0f - __fdividef(2.0f, __expf(2.0f * x) + 1.0f);
}

// ---- packed f32x2 helpers (Blackwell) ----
__device__ __forceinline__ unsigned long long pk2(float lo, float hi) {
    unsigned long long r;
    asm("mov.b64 %0, {%1, %2};" : "=l"(r) : "f"(lo), "f"(hi));
    return r;
}
__device__ __forceinline__ void upk2(unsigned long long v, float& lo, float& hi) {
    asm("mov.b64 {%0, %1}, %2;" : "=f"(lo), "=f"(hi) : "l"(v));
}
__device__ __forceinline__ unsigned long long ffma2(
    unsigned long long a, unsigned long long b, unsigned long long c) {
    unsigned long long d;
    asm("fma.rn.f32x2 %0, %1, %2, %3;" : "=l"(d) : "l"(a), "l"(b), "l"(c));
    return d;
}

// ---- cp.async helpers ----
__device__ __forceinline__ void cp_async16(unsigned int daddr, const void* saddr) {
    asm volatile("cp.async.cg.shared.global [%0], [%1], 16;"
                 :: "r"(daddr), "l"(saddr) : "memory");
}
__device__ __forceinline__ void cp_commit() {
    asm volatile("cp.async.commit_group;" ::: "memory");
}
template <int N>
__device__ __forceinline__ void cp_wait() {
    asm volatile("cp.async.wait_group %0;" :: "n"(N) : "memory");
}

// ---------------------------------------------------------------------------
// Input-projection GEMM with a double-buffered cp.async tile pipeline.
// Grid = 256 blocks (single resident wave). Each block owns NT=16 tiles of
// ROWS=64 input rows: while computing tile i, tile i+1 streams into the
// other SMEM buffer. Inner math identical to the proven R2 GEMM.
// ---------------------------------------------------------------------------
template <int IN, int G, int MINB>
__global__ void __launch_bounds__(G, MINB) gemm_xg_kernel(
    const float* __restrict__ in, const float* __restrict__ Wih,
    const float* __restrict__ bih, const float* __restrict__ bhh,
    float* __restrict__ xg)
{
    constexpr int ROWS = 64;
    constexpr int NT = 16;                 // tiles per block (grid 256 -> 4096 tiles)
    constexpr int NV = ROWS * IN / 4;      // float4 chunks per tile
    __shared__ __align__(16) float sIn[2][ROWS * IN];

    const int g = threadIdx.x;
    const size_t tile0 = (size_t)blockIdx.x * NT;

    unsigned long long w2[IN / 2];
    {
        const unsigned long long* wp = (const unsigned long long*)(Wih + (size_t)g * IN);
#pragma unroll
        for (int i = 0; i < IN / 2; i++) w2[i] = wp[i];
    }
    const float bias = bih[g] + bhh[g];

    const unsigned int sbase = (unsigned int)__cvta_generic_to_shared(&sIn[0][0]);

    // prologue: stage tile 0 into buffer 0
    {
        const float4* src = (const float4*)(in + tile0 * ROWS * IN);
        for (int i = g; i < NV; i += G)
            cp_async16(sbase + (unsigned int)i * 16u, src + i);
        cp_commit();
    }

#pragma unroll 1
    for (int it = 0; it < NT; it++) {
        const int buf = it & 1;

        // stage tile it+1 into the other buffer (it was last read at it-1,
        // protected by the trailing barrier of that iteration)
        if (it + 1 < NT) {
            const float4* src = (const float4*)(in + (tile0 + it + 1) * ROWS * IN);
            const unsigned int dst = sbase + (unsigned int)(buf ^ 1) * (ROWS * IN * 4u);
            for (int i = g; i < NV; i += G)
                cp_async16(dst + (unsigned int)i * 16u, src + i);
            cp_commit();
            cp_wait<1>();   // tile it complete (one group may stay in flight)
        } else {
            cp_wait<0>();
        }
        __syncthreads();

        float* outp = xg + (tile0 + it) * ROWS * G + g;
        const float* sb = sIn[buf];
#pragma unroll 1
        for (int r = 0; r < ROWS; r++) {
            unsigned long long accA = pk2(bias, 0.0f);
            unsigned long long accB = pk2(0.0f, 0.0f);
            const ulonglong2* rp = (const ulonglong2*)(sb + r * IN);
#pragma unroll
            for (int i = 0; i < IN / 4; i++) {
                ulonglong2 v = rp[i];
                accA = ffma2(w2[2 * i + 0], v.x, accA);
                accB = ffma2(w2[2 * i + 1], v.y, accB);
            }
            float a0, a1, b0, b1;
            upk2(accA, a0, a1);
            upk2(accB, b0, b1);
            outp[(size_t)r * G] = (a0 + a1) + (b0 + b1);
        }
        __syncthreads();
    }
}

// ---------------------------------------------------------------------------
// Recurrent scan (proven R15 version): R2 structure + register-ring xg
// prefetch, depth D per layer (H=32 -> D=4; H=64/72 -> D=2, L0 I$ bound).
// ---------------------------------------------------------------------------
template <int H, int R, int MINB, int D>
__global__ void __launch_bounds__(4 * H, MINB) lstm_rec_kernel(
    const float* __restrict__ xg, const float* __restrict__ Whh,
    float* __restrict__ hout)
{
    constexpr int G4 = 4 * H;
    __shared__ __align__(16) float h_sm[R * H];
    __shared__ float g_sm[R * G4];

    const int j = threadIdx.x;
    const int b0 = blockIdx.x * R;
    const int gate = j / H;

    unsigned long long w2[H / 2];
    {
        const unsigned long long* wp = (const unsigned long long*)(Whh + (size_t)j * H);
#pragma unroll
        for (int k = 0; k < H / 2; k++) w2[k] = wp[k];
    }

    for (int i = j; i < R * H; i += G4) h_sm[i] = 0.0f;
    float c = 0.0f;

    const float* xgp = xg + (size_t)b0 * Tn * G4 + j;
    float* hp = hout + (size_t)b0 * Tn * H;

    const int cr = j / H;  // cell-update mapping (first R*H threads)
    const int cm = j % H;

    float xn[R][D];
#pragma unroll
    for (int u = 0; u < D; u++)
#pragma unroll
        for (int r = 0; r < R; r++)
            xn[r][u] = xgp[((size_t)r * Tn + u) * G4];

    __syncthreads();

#pragma unroll 1
    for (int t = 0; t < Tn; t += D) {
#pragma unroll
        for (int u = 0; u < D; u++) {
            const int tt = t + u;

            unsigned long long acc[R];
#pragma unroll
            for (int r = 0; r < R; r++) acc[r] = pk2(xn[r][u], 0.0f);

            if (tt + D < Tn) {
#pragma unroll
                for (int r = 0; r < R; r++)
                    xn[r][u] = xgp[((size_t)r * Tn + tt + D) * G4];
            }

#pragma unroll
            for (int k = 0; k < H / 4; k++) {
#pragma unroll
                for (int r = 0; r < R; r++) {
                    ulonglong2 hv = ((const ulonglong2*)&h_sm[r * H])[k];
                    acc[r] = ffma2(w2[2 * k + 0], hv.x, acc[r]);
                    acc[r] = ffma2(w2[2 * k + 1], hv.y, acc[r]);
                }
            }

#pragma unroll
            for (int r = 0; r < R; r++) {
                float lo, hi;
                upk2(acc[r], lo, hi);
                float a = lo + hi;
                a = (gate == 2) ? ftanh(a) : fsig(a);
                g_sm[r * G4 + j] = a;
            }
            __syncthreads();

            if (j < R * H) {
                const float iv = g_sm[cr * G4 + 0 * H + cm];
                const float fv = g_sm[cr * G4 + 1 * H + cm];
                const float gv = g_sm[cr * G4 + 2 * H + cm];
                const float ov = g_sm[cr * G4 + 3 * H + cm];
                c = fv * c + iv * gv;
                const float h = ov * ftanh(c);
                h_sm[cr * H + cm] = h;
                hp[((size_t)cr * Tn + tt) * H + cm] = h;
            }
            __syncthreads();
        }
    }
}

// ---------------------------------------------------------------------------
extern "C" void kernel_launch(void* const* d_in, const int* in_sizes, int n_in,
                              void* d_out, int out_size)
{
    (void)in_sizes; (void)n_in; (void)out_size;

    const float* x    = (const float*)d_in[0];
    const float* e1W  = (const float*)d_in[1];
    const float* e1U  = (const float*)d_in[2];
    const float* e1bi = (const float*)d_in[3];
    const float* e1bh = (const float*)d_in[4];
    const float* e2W  = (const float*)d_in[5];
    const float* e2U  = (const float*)d_in[6];
    const float* e2bi = (const float*)d_in[7];
    const float* e2bh = (const float*)d_in[8];
    const float* d1W  = (const float*)d_in[9];
    const float* d1U  = (const float*)d_in[10];
    const float* d1bi = (const float*)d_in[11];
    const float* d1bh = (const float*)d_in[12];
    const float* d2W  = (const float*)d_in[13];
    const float* d2U  = (const float*)d_in[14];
    const float* d2bi = (const float*)d_in[15];
    const float* d2bh = (const float*)d_in[16];
    float* out = (float*)d_out;

    float *xg = nullptr, *sa = nullptr, *sb = nullptr;
    cudaGetSymbolAddress((void**)&xg, g_xg);
    cudaGetSymbolAddress((void**)&sa, g_seqA);
    cudaGetSymbolAddress((void**)&sb, g_seqB);

    const int gemmGrid = 256;  // NT=16 tiles of 64 rows each -> 262144 rows

    // e1: 72 -> 64
    gemm_xg_kernel<72, 256, 2><<<gemmGrid, 256>>>(x, e1W, e1bi, e1bh, xg);
    lstm_rec_kernel<64, 2, 2, 2><<<Bn / 2, 256>>>(xg, e1U, sa);
    // e2: 64 -> 32
    gemm_xg_kernel<64, 128, 3><<<gemmGrid, 128>>>(sa, e2W, e2bi, e2bh, xg);
    lstm_rec_kernel<32, 1, 4, 4><<<Bn, 128>>>(xg, e2U, sb);
    // d1: 32 -> 64
    gemm_xg_kernel<32, 256, 2><<<gemmGrid, 256>>>(sb, d1W, d1bi, d1bh, xg);
    lstm_rec_kernel<64, 2, 2, 2><<<Bn / 2, 256>>>(xg, d1U, sa);
    // d2: 64 -> 72
    gemm_xg_kernel<64, 288, 2><<<gemmGrid, 288>>>(sa, d2W, d2bi, d2bh, xg);
    lstm_rec_kernel<72, 2, 2, 2><<<Bn / 2, 288>>>(xg, d2U, out);
}